// round 2
// baseline (speedup 1.0000x reference)
#include <cuda_runtime.h>
#include <cuda_bf16.h>

#define N_NODES 50000
#define FDIM 128
#define E_EDGES 800000

// Scratch (static __device__ arrays — no allocations allowed). 16B-aligned for
// float4 / red.v4 access.
__device__ __align__(16) float g_agg[N_NODES * FDIM];      // 25.6 MB
__device__ __align__(16) float g_cnt[N_NODES];
__device__ __align__(16) float g_h1[N_NODES * FDIM];       // 25.6 MB
__device__ __align__(16) float g_h2[N_NODES * FDIM];       // 25.6 MB
__device__ __align__(16) float g_ab[N_NODES * 512];        // 102.4 MB : [A(256) | B(256)] per node

// ---------------------------------------------------------------------------
// Zero agg + cnt
// ---------------------------------------------------------------------------
__global__ void zero_kernel() {
    int i = blockIdx.x * blockDim.x + threadIdx.x;
    if (i < N_NODES * FDIM) g_agg[i] = 0.0f;
    if (i < N_NODES) g_cnt[i] = 0.0f;
}

// ---------------------------------------------------------------------------
// Scatter: warp per edge. agg[dst] += x[src], cnt[dst] += 1
// edge_index is int32 (JAX x64-disabled downcasts int64 -> int32).
// ---------------------------------------------------------------------------
__global__ void scatter_kernel(const float4* __restrict__ x,
                               const int* __restrict__ ei) {
    int w = (blockIdx.x * blockDim.x + threadIdx.x) >> 5;
    int lane = threadIdx.x & 31;
    if (w >= E_EDGES) return;
    int s = ei[w];
    int d = ei[E_EDGES + w];
    float4 v = x[(long long)s * 32 + lane];
    float* p = g_agg + ((long long)d * FDIM + lane * 4);
    asm volatile("red.global.add.v4.f32 [%0], {%1,%2,%3,%4};"
                 :: "l"(p), "f"(v.x), "f"(v.y), "f"(v.z), "f"(v.w) : "memory");
    if (lane == 0) atomicAdd(g_cnt + d, 1.0f);
}

// ---------------------------------------------------------------------------
// Normalize agg by max(cnt, 1)
// ---------------------------------------------------------------------------
__global__ void norm_kernel() {
    int i = blockIdx.x * blockDim.x + threadIdx.x;   // over N*32 float4
    if (i >= N_NODES * 32) return;
    int row = i >> 5;
    float sc = 1.0f / fmaxf(g_cnt[row], 1.0f);
    float4* agg4 = reinterpret_cast<float4*>(g_agg);
    float4 v = agg4[i];
    v.x *= sc; v.y *= sc; v.z *= sc; v.w *= sc;
    agg4[i] = v;
}

// ---------------------------------------------------------------------------
// Fused GEMM: C[r, j] = act( sum_k A1[r,k]*W1[j,k] (+ A2[r,k]*W2[j,k]) + bias[j] )
//   DUAL:   logical K = 256 (first 128 from A1/W1, second from A2/W2)
//   SPLITW: dout = 512, K = 128, W element for col j:
//           Wm1[(j&255)*256 + (j>>8)*128 + k]   (A-part j<256, B-part j>=256)
//   bias applied only for col < bias_len
// BM = BN = 128, BK = 16, 256 threads, 8x8 per-thread tile.
// ---------------------------------------------------------------------------
template<bool DUAL, bool RELU, bool SPLITW>
__global__ __launch_bounds__(256, 2)
void gemm_kernel(const float* __restrict__ A1, const float* __restrict__ A2,
                 const float* __restrict__ W1, const float* __restrict__ W2,
                 const float* __restrict__ bias, int bias_len,
                 float* __restrict__ C, int n_rows, int dout) {
    const int BM = 128, BN = 128, BK = 16;
    const int KT = DUAL ? 256 : 128;
    __shared__ float As[BK][BM + 4];
    __shared__ float Bs[BK][BN + 4];

    int tid = threadIdx.x;
    int tx = tid & 15;       // col group
    int ty = tid >> 4;       // row group
    int r0 = blockIdx.x * BM;
    int n0 = blockIdx.y * BN;

    float c[8][8];
#pragma unroll
    for (int i = 0; i < 8; i++)
#pragma unroll
        for (int j = 0; j < 8; j++) c[i][j] = 0.0f;

    for (int k0 = 0; k0 < KT; k0 += BK) {
        const float* Asrc; const float* Wsrc; int kb;
        if (DUAL && k0 >= 128) { Asrc = A2; Wsrc = W2; kb = k0 - 128; }
        else                   { Asrc = A1; Wsrc = W1; kb = k0; }

        // Stage tiles (transposed into smem)
#pragma unroll
        for (int j = 0; j < 2; j++) {
            int id  = tid * 2 + j;
            int row = id >> 2;           // 0..127
            int kk  = (id & 3) * 4;      // 0,4,8,12
            // A tile
            int r = r0 + row;
            float4 g = make_float4(0.f, 0.f, 0.f, 0.f);
            if (r < n_rows)
                g = *reinterpret_cast<const float4*>(Asrc + (long long)r * FDIM + kb + kk);
            As[kk + 0][row] = g.x; As[kk + 1][row] = g.y;
            As[kk + 2][row] = g.z; As[kk + 3][row] = g.w;
            // W tile (cols always in-bounds: dout % 128 == 0)
            int jcol = n0 + row;
            float4 h;
            if (SPLITW) {
                int wr = jcol & 255;
                int ko = (jcol >> 8) * 128;
                h = *reinterpret_cast<const float4*>(W1 + wr * 256 + ko + kb + kk);
            } else {
                h = *reinterpret_cast<const float4*>(Wsrc + (long long)jcol * FDIM + kb + kk);
            }
            Bs[kk + 0][row] = h.x; Bs[kk + 1][row] = h.y;
            Bs[kk + 2][row] = h.z; Bs[kk + 3][row] = h.w;
        }
        __syncthreads();

#pragma unroll
        for (int k = 0; k < BK; k++) {
            float a[8], b[8];
            *reinterpret_cast<float4*>(a)     = *reinterpret_cast<const float4*>(&As[k][ty * 8]);
            *reinterpret_cast<float4*>(a + 4) = *reinterpret_cast<const float4*>(&As[k][ty * 8 + 4]);
            *reinterpret_cast<float4*>(b)     = *reinterpret_cast<const float4*>(&Bs[k][tx * 8]);
            *reinterpret_cast<float4*>(b + 4) = *reinterpret_cast<const float4*>(&Bs[k][tx * 8 + 4]);
#pragma unroll
            for (int i = 0; i < 8; i++)
#pragma unroll
                for (int j = 0; j < 8; j++) c[i][j] += a[i] * b[j];
        }
        __syncthreads();
    }

    // Epilogue
#pragma unroll
    for (int i = 0; i < 8; i++) {
        int r = r0 + ty * 8 + i;
        if (r >= n_rows) break;
#pragma unroll
        for (int j = 0; j < 8; j++) {
            int col = n0 + tx * 8 + j;
            float v = c[i][j];
            if (bias != nullptr && col < bias_len) v += bias[col];
            if (RELU) v = fmaxf(v, 0.0f);
            C[(long long)r * dout + col] = v;
        }
    }
}

// ---------------------------------------------------------------------------
// Edge MLP epilogue: out[e] = sum_j relu(A[src,j] + B[dst,j]) * w2[j] + b2
// A = g_ab[:, 0:256] (bias bm1 folded in), B = g_ab[:, 256:512]
// Warp per edge.
// ---------------------------------------------------------------------------
__global__ void edge_kernel(const int* __restrict__ ei,
                            const float4* __restrict__ w2,
                            const float* __restrict__ b2,
                            float* __restrict__ out) {
    int w = (blockIdx.x * blockDim.x + threadIdx.x) >> 5;
    int lane = threadIdx.x & 31;
    if (w >= E_EDGES) return;
    int s = ei[w];
    int d = ei[E_EDGES + w];
    const float4* ab4 = reinterpret_cast<const float4*>(g_ab);
    const float4* pa = ab4 + (long long)s * 128;        // A part: float4 0..63
    const float4* pb = ab4 + (long long)d * 128 + 64;   // B part: float4 64..127
    float acc = 0.0f;
#pragma unroll
    for (int u = 0; u < 2; u++) {
        float4 a  = pa[u * 32 + lane];
        float4 b  = pb[u * 32 + lane];
        float4 wv = w2[u * 32 + lane];
        acc += fmaxf(a.x + b.x, 0.0f) * wv.x;
        acc += fmaxf(a.y + b.y, 0.0f) * wv.y;
        acc += fmaxf(a.z + b.z, 0.0f) * wv.z;
        acc += fmaxf(a.w + b.w, 0.0f) * wv.w;
    }
#pragma unroll
    for (int o = 16; o; o >>= 1) acc += __shfl_xor_sync(0xffffffffu, acc, o);
    if (lane == 0) out[w] = acc + b2[0];
}

// ---------------------------------------------------------------------------
extern "C" void kernel_launch(void* const* d_in, const int* in_sizes, int n_in,
                              void* d_out, int out_size) {
    const float* x   = (const float*)d_in[0];
    const int*   ei  = (const int*)d_in[1];     // int32! (JAX x64 disabled)
    const float* W1l = (const float*)d_in[2];
    const float* b1l = (const float*)d_in[3];
    const float* W1r = (const float*)d_in[4];
    const float* W2l = (const float*)d_in[5];
    const float* b2l = (const float*)d_in[6];
    const float* W2r = (const float*)d_in[7];
    const float* Wm1 = (const float*)d_in[8];
    const float* bm1 = (const float*)d_in[9];
    const float* Wm2 = (const float*)d_in[10];
    const float* bm2 = (const float*)d_in[11];
    float*       out = (float*)d_out;

    void *p_agg, *p_h1, *p_h2, *p_ab;
    cudaGetSymbolAddress(&p_agg, g_agg);
    cudaGetSymbolAddress(&p_h1, g_h1);
    cudaGetSymbolAddress(&p_h2, g_h2);
    cudaGetSymbolAddress(&p_ab, g_ab);
    float* agg = (float*)p_agg;
    float* h1  = (float*)p_h1;
    float* h2  = (float*)p_h2;
    float* ab  = (float*)p_ab;

    const int ZB  = (N_NODES * FDIM + 255) / 256;      // 25000
    const int SB  = (E_EDGES * 32) / 256;              // 100000
    const int NB  = (N_NODES * 32 + 255) / 256;        // 6250
    const int GBX = (N_NODES + 127) / 128;             // 391

    // ---- Layer 1 ----
    zero_kernel<<<ZB, 256>>>();
    scatter_kernel<<<SB, 256>>>(reinterpret_cast<const float4*>(x), ei);
    norm_kernel<<<NB, 256>>>();
    gemm_kernel<true, true, false><<<dim3(GBX, 1), 256>>>(
        agg, x, W1l, W1r, b1l, 128, h1, N_NODES, 128);

    // ---- Layer 2 ----
    zero_kernel<<<ZB, 256>>>();
    scatter_kernel<<<SB, 256>>>(reinterpret_cast<const float4*>(h1), ei);
    norm_kernel<<<NB, 256>>>();
    gemm_kernel<true, true, false><<<dim3(GBX, 1), 256>>>(
        agg, h1, W2l, W2r, b2l, 128, h2, N_NODES, 128);

    // ---- Edge MLP, factorized: AB = h2 @ [Wm1_left | Wm1_right].T (+bm1 on A half) ----
    gemm_kernel<false, false, true><<<dim3(GBX, 4), 256>>>(
        h2, nullptr, Wm1, nullptr, bm1, 256, ab, N_NODES, 512);

    edge_kernel<<<SB, 256>>>(ei, reinterpret_cast<const float4*>(Wm2), bm2, out);
}

// round 3
// speedup vs baseline: 1.2767x; 1.2767x over previous
#include <cuda_runtime.h>
#include <cuda_bf16.h>
#include <cstdint>

#define N_NODES 50000
#define FDIM 128
#define E_EDGES 800000

// Scratch (static __device__ arrays — no allocations allowed). 16B-aligned.
__device__ __align__(16) float g_agg[N_NODES * FDIM];      // 25.6 MB
__device__ __align__(16) float g_cnt[N_NODES];
__device__ __align__(16) float g_h1[N_NODES * FDIM];       // 25.6 MB
__device__ __align__(16) float g_h2[N_NODES * FDIM];       // 25.6 MB
__device__ __align__(16) float g_ab[N_NODES * 512];        // 102.4 MB : [A(256) | B(256)]

// ---------------------------------------------------------------------------
__global__ void zero_kernel() {
    int i = blockIdx.x * blockDim.x + threadIdx.x;
    if (i < N_NODES * FDIM) g_agg[i] = 0.0f;
    if (i < N_NODES) g_cnt[i] = 0.0f;
}

// ---------------------------------------------------------------------------
// Scatter: warp per edge. agg[dst] += x[src], cnt[dst] += 1  (edge_index int32)
// ---------------------------------------------------------------------------
__global__ void scatter_kernel(const float4* __restrict__ x,
                               const int* __restrict__ ei) {
    int w = (blockIdx.x * blockDim.x + threadIdx.x) >> 5;
    int lane = threadIdx.x & 31;
    if (w >= E_EDGES) return;
    int s = ei[w];
    int d = ei[E_EDGES + w];
    float4 v = x[(long long)s * 32 + lane];
    float* p = g_agg + ((long long)d * FDIM + lane * 4);
    asm volatile("red.global.add.v4.f32 [%0], {%1,%2,%3,%4};"
                 :: "l"(p), "f"(v.x), "f"(v.y), "f"(v.z), "f"(v.w) : "memory");
    if (lane == 0) atomicAdd(g_cnt + d, 1.0f);
}

// ---------------------------------------------------------------------------
__global__ void norm_kernel() {
    int i = blockIdx.x * blockDim.x + threadIdx.x;   // over N*32 float4
    if (i >= N_NODES * 32) return;
    int row = i >> 5;
    float sc = 1.0f / fmaxf(g_cnt[row], 1.0f);
    float4* agg4 = reinterpret_cast<float4*>(g_agg);
    float4 v = agg4[i];
    v.x *= sc; v.y *= sc; v.z *= sc; v.w *= sc;
    agg4[i] = v;
}

// ---------------------------------------------------------------------------
// Tensor-core GEMM (tf32 mma.sync, A split hi/lo, W single-rounded tf32)
//   C[r, j] = act( sum_k A1[r,k]*W1[j,k] (+ A2[r,k]*W2[j,k]) + bias[j] )
//   DUAL:   logical K = 256 (first 128 from A1/W1, second from A2/W2)
//   SPLITW: dout = 512, K = 128; W element for col j: Wm1[(j&255)*256 + (j>>8)*128 + k]
// BM=BN=128, BK=32, 256 threads (8 warps: 4 in M x 2 in N), warp tile 32x64.
// Smem holds fragment-permuted tiles so compute does conflict-free lds.128/lds.64.
// ---------------------------------------------------------------------------
__device__ __forceinline__ float tf32r(float v) {
    uint32_t u;
    asm("cvt.rna.tf32.f32 %0, %1;" : "=r"(u) : "f"(v));
    return __uint_as_float(u);
}

__device__ __forceinline__ void mma_tf32(float4& c, const float4 a, const float2 b) {
    asm volatile(
        "mma.sync.aligned.m16n8k8.row.col.f32.tf32.tf32.f32 "
        "{%0,%1,%2,%3}, {%4,%5,%6,%7}, {%8,%9}, {%0,%1,%2,%3};\n"
        : "+f"(c.x), "+f"(c.y), "+f"(c.z), "+f"(c.w)
        : "r"(__float_as_uint(a.x)), "r"(__float_as_uint(a.y)),
          "r"(__float_as_uint(a.z)), "r"(__float_as_uint(a.w)),
          "r"(__float_as_uint(b.x)), "r"(__float_as_uint(b.y)));
}

template<bool DUAL, bool RELU, bool SPLITW>
__global__ __launch_bounds__(256, 2)
void gemm_kernel(const float* __restrict__ A1, const float* __restrict__ A2,
                 const float* __restrict__ W1, const float* __restrict__ W2,
                 const float* __restrict__ bias, int bias_len,
                 float* __restrict__ C, int n_rows, int dout) {
    __shared__ float sAhi[4096];   // 8 mtiles x 4 ksteps, 128 floats each (lane*4+reg)
    __shared__ float sAlo[4096];
    __shared__ float sB[4096];     // 16 ntiles x 4 ksteps, 64 floats each (lane*2+reg)

    const int tid = threadIdx.x;
    const int lane = tid & 31;
    const int wid = tid >> 5;
    const int wm = wid & 3;        // warp row group (32 rows)
    const int wn = wid >> 2;       // warp col group (64 cols)
    const int r0 = blockIdx.x * 128;
    const int n0 = blockIdx.y * 128;
    const int NKT = DUAL ? 8 : 4;  // 32-wide k tiles

    float4 acc[2][8];
#pragma unroll
    for (int i = 0; i < 2; i++)
#pragma unroll
        for (int j = 0; j < 8; j++) acc[i][j] = make_float4(0.f, 0.f, 0.f, 0.f);

    for (int kt = 0; kt < NKT; kt++) {
        const float* Asrc = (DUAL && kt >= 4) ? A2 : A1;
        const float* Wsrc = (DUAL && kt >= 4) ? W2 : W1;
        const int kb = (kt & 3) * 32;

        __syncthreads();
        // ---- stage A (hi/lo) and B (tf32) into permuted smem ----
#pragma unroll
        for (int it = 0; it < 4; it++) {
            int id  = tid + it * 256;   // 0..1023
            int row = id >> 3;          // 0..127
            int c0  = (id & 7) * 4;     // 0,4,...,28
            int ks  = c0 >> 3;
            // A tile
            int r = r0 + row;
            float4 gA = make_float4(0.f, 0.f, 0.f, 0.f);
            if (r < n_rows)
                gA = *reinterpret_cast<const float4*>(Asrc + (size_t)r * FDIM + kb + c0);
            {
                int regb = (((row & 15) >= 8) ? 1 : 0) + (((c0 & 7) >= 4) ? 2 : 0);
                int tb   = (ks * 8 + (row >> 4)) * 128;
                int lb   = (row & 7) * 4;
                float v[4] = {gA.x, gA.y, gA.z, gA.w};
#pragma unroll
                for (int j = 0; j < 4; j++) {
                    float hi = tf32r(v[j]);
                    sAhi[tb + (lb + j) * 4 + regb] = hi;
                    sAlo[tb + (lb + j) * 4 + regb] = tf32r(v[j] - hi);
                }
            }
            // B tile (cols always in-bounds: dout % 128 == 0)
            {
                int jcol = n0 + row;
                const float* wp;
                if (SPLITW) wp = W1 + (jcol & 255) * 256 + ((jcol >> 8) * 128) + kb + c0;
                else        wp = Wsrc + (size_t)jcol * FDIM + kb + c0;
                float4 gB = *reinterpret_cast<const float4*>(wp);
                int bb   = (ks * 16 + (row >> 3)) * 64;
                int blb  = (row & 7) * 4;
                int bre  = ((c0 & 7) >= 4) ? 1 : 0;
                float v[4] = {gB.x, gB.y, gB.z, gB.w};
#pragma unroll
                for (int j = 0; j < 4; j++)
                    sB[bb + (blb + j) * 2 + bre] = tf32r(v[j]);
            }
        }
        __syncthreads();

        // ---- compute: 4 k-steps of m16n8k8 ----
#pragma unroll
        for (int ks = 0; ks < 4; ks++) {
            float4 ahi[2], alo[2];
#pragma unroll
            for (int mt2 = 0; mt2 < 2; mt2++) {
                int base = ((ks * 8 + wm * 2 + mt2) * 32 + lane) * 4;
                ahi[mt2] = *reinterpret_cast<const float4*>(sAhi + base);
                alo[mt2] = *reinterpret_cast<const float4*>(sAlo + base);
            }
#pragma unroll
            for (int nt2 = 0; nt2 < 8; nt2++) {
                float2 b = *reinterpret_cast<const float2*>(
                    sB + (ks * 16 + wn * 8 + nt2) * 64 + lane * 2);
#pragma unroll
                for (int mt2 = 0; mt2 < 2; mt2++) {
                    mma_tf32(acc[mt2][nt2], ahi[mt2], b);
                    mma_tf32(acc[mt2][nt2], alo[mt2], b);
                }
            }
        }
    }

    // ---- epilogue ----
    const int g = lane >> 2, tg = lane & 3;
#pragma unroll
    for (int mt2 = 0; mt2 < 2; mt2++) {
        int Rb = r0 + (wm * 2 + mt2) * 16;
#pragma unroll
        for (int nt2 = 0; nt2 < 8; nt2++) {
            int Cb = n0 + (wn * 8 + nt2) * 8;
            float4 c = acc[mt2][nt2];
            float2 bv = make_float2(0.f, 0.f);
            if (bias != nullptr && Cb < bias_len)
                bv = *reinterpret_cast<const float2*>(bias + Cb + tg * 2);
            float2 lo = make_float2(c.x + bv.x, c.y + bv.y);
            float2 hi = make_float2(c.z + bv.x, c.w + bv.y);
            if (RELU) {
                lo.x = fmaxf(lo.x, 0.f); lo.y = fmaxf(lo.y, 0.f);
                hi.x = fmaxf(hi.x, 0.f); hi.y = fmaxf(hi.y, 0.f);
            }
            int r1 = Rb + g, r2 = Rb + g + 8;
            if (r1 < n_rows)
                *reinterpret_cast<float2*>(C + (size_t)r1 * dout + Cb + tg * 2) = lo;
            if (r2 < n_rows)
                *reinterpret_cast<float2*>(C + (size_t)r2 * dout + Cb + tg * 2) = hi;
        }
    }
}

// ---------------------------------------------------------------------------
// Edge MLP epilogue: out[e] = sum_j relu(A[src,j] + B[dst,j]) * w2[j] + b2
// ---------------------------------------------------------------------------
__global__ void edge_kernel(const int* __restrict__ ei,
                            const float4* __restrict__ w2,
                            const float* __restrict__ b2,
                            float* __restrict__ out) {
    int w = (blockIdx.x * blockDim.x + threadIdx.x) >> 5;
    int lane = threadIdx.x & 31;
    if (w >= E_EDGES) return;
    int s = ei[w];
    int d = ei[E_EDGES + w];
    const float4* ab4 = reinterpret_cast<const float4*>(g_ab);
    const float4* pa = ab4 + (long long)s * 128;        // A part: float4 0..63
    const float4* pb = ab4 + (long long)d * 128 + 64;   // B part: float4 64..127
    float acc = 0.0f;
#pragma unroll
    for (int u = 0; u < 2; u++) {
        float4 a  = pa[u * 32 + lane];
        float4 b  = pb[u * 32 + lane];
        float4 wv = w2[u * 32 + lane];
        acc += fmaxf(a.x + b.x, 0.0f) * wv.x;
        acc += fmaxf(a.y + b.y, 0.0f) * wv.y;
        acc += fmaxf(a.z + b.z, 0.0f) * wv.z;
        acc += fmaxf(a.w + b.w, 0.0f) * wv.w;
    }
#pragma unroll
    for (int o = 16; o; o >>= 1) acc += __shfl_xor_sync(0xffffffffu, acc, o);
    if (lane == 0) out[w] = acc + b2[0];
}

// ---------------------------------------------------------------------------
extern "C" void kernel_launch(void* const* d_in, const int* in_sizes, int n_in,
                              void* d_out, int out_size) {
    const float* x   = (const float*)d_in[0];
    const int*   ei  = (const int*)d_in[1];     // int32 (JAX x64 disabled)
    const float* W1l = (const float*)d_in[2];
    const float* b1l = (const float*)d_in[3];
    const float* W1r = (const float*)d_in[4];
    const float* W2l = (const float*)d_in[5];
    const float* b2l = (const float*)d_in[6];
    const float* W2r = (const float*)d_in[7];
    const float* Wm1 = (const float*)d_in[8];
    const float* bm1 = (const float*)d_in[9];
    const float* Wm2 = (const float*)d_in[10];
    const float* bm2 = (const float*)d_in[11];
    float*       out = (float*)d_out;

    void *p_agg, *p_h1, *p_h2, *p_ab;
    cudaGetSymbolAddress(&p_agg, g_agg);
    cudaGetSymbolAddress(&p_h1, g_h1);
    cudaGetSymbolAddress(&p_h2, g_h2);
    cudaGetSymbolAddress(&p_ab, g_ab);
    float* agg = (float*)p_agg;
    float* h1  = (float*)p_h1;
    float* h2  = (float*)p_h2;
    float* ab  = (float*)p_ab;

    const int ZB  = (N_NODES * FDIM + 255) / 256;      // 25000
    const int SB  = (E_EDGES * 32) / 256;              // 100000
    const int NB  = (N_NODES * 32 + 255) / 256;        // 6250
    const int GBX = (N_NODES + 127) / 128;             // 391

    // ---- Layer 1 ----
    zero_kernel<<<ZB, 256>>>();
    scatter_kernel<<<SB, 256>>>(reinterpret_cast<const float4*>(x), ei);
    norm_kernel<<<NB, 256>>>();
    gemm_kernel<true, true, false><<<dim3(GBX, 1), 256>>>(
        agg, x, W1l, W1r, b1l, 128, h1, N_NODES, 128);

    // ---- Layer 2 ----
    zero_kernel<<<ZB, 256>>>();
    scatter_kernel<<<SB, 256>>>(reinterpret_cast<const float4*>(h1), ei);
    norm_kernel<<<NB, 256>>>();
    gemm_kernel<true, true, false><<<dim3(GBX, 1), 256>>>(
        agg, h1, W2l, W2r, b2l, 128, h2, N_NODES, 128);

    // ---- Edge MLP, factorized: AB = h2 @ [Wm1_left | Wm1_right].T (+bm1 on A half) ----
    gemm_kernel<false, false, true><<<dim3(GBX, 4), 256>>>(
        h2, nullptr, Wm1, nullptr, bm1, 256, ab, N_NODES, 512);

    edge_kernel<<<SB, 256>>>(ei, reinterpret_cast<const float4*>(Wm2), bm2, out);
}